// round 15
// baseline (speedup 1.0000x reference)
#include <cuda_runtime.h>
#include <cuda_bf16.h>
#include <cstdint>

#define T_STEPS 512
#define BATCH   64
#define DIN     128
#define DH      1024
#define DOUT    256
#define RANK    64

#define CL      4            // cluster size (CTAs per batch-pair)
#define COLS    256          // DH / CL columns per CTA
#define BGRP    2            // batch elements per cluster

// ---------------- bf16x3 split-GEMM via mma.sync (HMMA) ----------------------
// C[m,n] = bias[n] + sum_k A[m,k]*B[n,k],  A:[M,K] row-major, B:[N,K] row-major.
// fp32 operands split in-kernel into bf16 hi+lo; C = Ah*Bh + Ah*Bl + Al*Bh.
// Tile 128x128, K-chunk 32, 8 warps (4m x 2n), warp = 32x64 = 2x8 m16n8k16.
// Register-prefetch pipeline: next chunk's fp32 tiles ride in regs during MMA.
#define KT 32
#define KPAD 40              // bf16 row stride (80 B): conflict-free frag loads

__device__ __forceinline__ void store_split(__nv_bfloat16* hp,
                                            __nv_bfloat16* lp, float4 v) {
    __nv_bfloat16 h0 = __float2bfloat16(v.x);
    __nv_bfloat16 h1 = __float2bfloat16(v.y);
    __nv_bfloat16 h2 = __float2bfloat16(v.z);
    __nv_bfloat16 h3 = __float2bfloat16(v.w);
    __nv_bfloat16 l0 = __float2bfloat16(v.x - __bfloat162float(h0));
    __nv_bfloat16 l1 = __float2bfloat16(v.y - __bfloat162float(h1));
    __nv_bfloat16 l2 = __float2bfloat16(v.z - __bfloat162float(h2));
    __nv_bfloat16 l3 = __float2bfloat16(v.w - __bfloat162float(h3));
    uint2 uh, ul;
    uh.x = ((uint32_t)__bfloat16_as_ushort(h1) << 16) | __bfloat16_as_ushort(h0);
    uh.y = ((uint32_t)__bfloat16_as_ushort(h3) << 16) | __bfloat16_as_ushort(h2);
    ul.x = ((uint32_t)__bfloat16_as_ushort(l1) << 16) | __bfloat16_as_ushort(l0);
    ul.y = ((uint32_t)__bfloat16_as_ushort(l3) << 16) | __bfloat16_as_ushort(l2);
    *(uint2*)hp = uh;
    *(uint2*)lp = ul;
}

__device__ __forceinline__ void mma16816(float* c, const uint32_t* a,
                                         const uint32_t* b) {
    asm volatile(
        "mma.sync.aligned.m16n8k16.row.col.f32.bf16.bf16.f32 "
        "{%0,%1,%2,%3}, {%4,%5,%6,%7}, {%8,%9}, {%0,%1,%2,%3};"
        : "+f"(c[0]), "+f"(c[1]), "+f"(c[2]), "+f"(c[3])
        : "r"(a[0]), "r"(a[1]), "r"(a[2]), "r"(a[3]), "r"(b[0]), "r"(b[1]));
}

__global__ void __launch_bounds__(256) mma_bt(const float* __restrict__ A,
                                              const float* __restrict__ Bm,
                                              const float* __restrict__ bias,
                                              float* __restrict__ C,
                                              int N, int K) {
    __shared__ __nv_bfloat16 sAh[128][KPAD], sAl[128][KPAD];
    __shared__ __nv_bfloat16 sBh[128][KPAD], sBl[128][KPAD];

    const int tid  = threadIdx.x;
    const int lane = tid & 31;
    const int w    = tid >> 5;
    const int wm   = w & 3;            // warp m 0..3 (32 rows each)
    const int wn   = w >> 2;           // warp n 0..1 (64 cols each)
    const int m0 = blockIdx.x * 128;
    const int n0 = blockIdx.y * 128;

    const int lrow = tid >> 1;         // loader row 0..127
    const int lk   = (tid & 1) * 16;   // loader k offset

    float acc[2][8][4];
#pragma unroll
    for (int mi = 0; mi < 2; mi++)
#pragma unroll
        for (int ni = 0; ni < 8; ni++)
#pragma unroll
            for (int q = 0; q < 4; q++) acc[mi][ni][q] = 0.0f;

    const int fr = lane >> 2;          // fragment row (0..7)
    const int fc = (lane & 3) * 2;     // fragment k-col base

    const float* arow = A + (size_t)(m0 + lrow) * K + lk;
    const float* brow = Bm + (size_t)(n0 + lrow) * K + lk;

    // ---- prologue: preload chunk 0 into registers ----
    float4 pa[4], pb[4];
#pragma unroll
    for (int j = 0; j < 4; j++) {
        pa[j] = *(const float4*)(arow + 4 * j);
        pb[j] = *(const float4*)(brow + 4 * j);
    }

#pragma unroll 1
    for (int kc = 0; kc < K; kc += KT) {
        // ---- split current chunk (already in regs) into SMEM ----
#pragma unroll
        for (int j = 0; j < 4; j++) {
            store_split(&sAh[lrow][lk + 4 * j], &sAl[lrow][lk + 4 * j], pa[j]);
            store_split(&sBh[lrow][lk + 4 * j], &sBl[lrow][lk + 4 * j], pb[j]);
        }
        __syncthreads();

        // ---- issue prefetch for chunk kc+KT (covered by the MMA block) ----
        if (kc + KT < K) {
            const float* apn = arow + kc + KT;
            const float* bpn = brow + kc + KT;
#pragma unroll
            for (int j = 0; j < 4; j++) {
                pa[j] = *(const float4*)(apn + 4 * j);
                pb[j] = *(const float4*)(bpn + 4 * j);
            }
        }

        // ---- 2 k16 steps, 2x8 tiles, 3 products each ----
#pragma unroll
        for (int ks = 0; ks < 2; ks++) {
            const int c = ks * 16 + fc;
            uint32_t ah[2][4], al[2][4], bh[8][2], bl[8][2];
#pragma unroll
            for (int mi = 0; mi < 2; mi++) {
                const int r = wm * 32 + mi * 16 + fr;
                ah[mi][0] = *(const uint32_t*)&sAh[r][c];
                ah[mi][1] = *(const uint32_t*)&sAh[r + 8][c];
                ah[mi][2] = *(const uint32_t*)&sAh[r][c + 8];
                ah[mi][3] = *(const uint32_t*)&sAh[r + 8][c + 8];
                al[mi][0] = *(const uint32_t*)&sAl[r][c];
                al[mi][1] = *(const uint32_t*)&sAl[r + 8][c];
                al[mi][2] = *(const uint32_t*)&sAl[r][c + 8];
                al[mi][3] = *(const uint32_t*)&sAl[r + 8][c + 8];
            }
#pragma unroll
            for (int ni = 0; ni < 8; ni++) {
                const int nn = wn * 64 + ni * 8 + fr;
                bh[ni][0] = *(const uint32_t*)&sBh[nn][c];
                bh[ni][1] = *(const uint32_t*)&sBh[nn][c + 8];
                bl[ni][0] = *(const uint32_t*)&sBl[nn][c];
                bl[ni][1] = *(const uint32_t*)&sBl[nn][c + 8];
            }
#pragma unroll
            for (int mi = 0; mi < 2; mi++)
#pragma unroll
                for (int ni = 0; ni < 8; ni++) {
                    mma16816(acc[mi][ni], ah[mi], bh[ni]);
                    mma16816(acc[mi][ni], ah[mi], bl[ni]);
                    mma16816(acc[mi][ni], al[mi], bh[ni]);
                }
        }
        __syncthreads();
    }

    // ---- epilogue: bias + store ----
#pragma unroll
    for (int mi = 0; mi < 2; mi++) {
        const int r0 = m0 + wm * 32 + mi * 16 + fr;
#pragma unroll
        for (int ni = 0; ni < 8; ni++) {
            const int col = n0 + wn * 64 + ni * 8 + (lane & 3) * 2;
            const float b0v = bias[col];
            const float b1v = bias[col + 1];
            float2 o0 = make_float2(acc[mi][ni][0] + b0v, acc[mi][ni][1] + b1v);
            float2 o1 = make_float2(acc[mi][ni][2] + b0v, acc[mi][ni][3] + b1v);
            *(float2*)&C[(size_t)r0 * N + col] = o0;
            *(float2*)&C[(size_t)(r0 + 8) * N + col] = o1;
        }
    }
}

// ---------------- common PTX helpers ----------------------------------------
__device__ __forceinline__ uint32_t smem_u32(const void* p) {
    uint32_t a;
    asm("{ .reg .u64 t; cvta.to.shared.u64 t, %1; cvt.u32.u64 %0, t; }"
        : "=r"(a) : "l"(p));
    return a;
}

// per-thread spin with CLUSTER-scope acquire: makes peers' DSMEM stores
// (release-ordered by their fence-before-arrive) visible without a separate
// fence + __syncthreads on the consumer side.
__device__ __forceinline__ void mbar_wait_acq_cluster(uint32_t mbar,
                                                      uint32_t parity) {
    asm volatile(
        "{\n\t"
        ".reg .pred P;\n\t"
        "W%=:\n\t"
        "mbarrier.try_wait.parity.acquire.cluster.shared::cta.b64 P, [%0], %1, 0x989680;\n\t"
        "@P bra D%=;\n\t"
        "bra W%=;\n\t"
        "D%=:\n\t"
        "}"
        :: "r"(mbar), "r"(parity) : "memory");
}

// ---------------- clustered recurrence (R8 core, trimmed consumer sync) ------
__global__ void __launch_bounds__(256, 1) __cluster_dims__(CL, 1, 1)
rnn_recur(const float* __restrict__ U, const float* __restrict__ V,
          float* __restrict__ hidden) {
    __shared__ __align__(16) float pbuf[2][CL][BGRP][RANK];
    __shared__ __align__(16) float pcur[BGRP][RANK];
    __shared__ __align__(16) float sH[BGRP][COLS];
    __shared__ __align__(16) float sTmp[CL][BGRP][RANK];
    __shared__ __align__(8) unsigned long long mbar;

    const int tid  = threadIdx.x;
    const int rank = blockIdx.x & (CL - 1);
    const int clus = blockIdx.x >> 2;
    const int b0   = clus * BGRP;
    const int colbase = rank * COLS;
    const int col  = colbase + tid;

    const int rr = tid & 63;
    const int qq = tid >> 6;

    float u[RANK];
#pragma unroll
    for (int r = 0; r < RANK; r += 4) {
        float4 t4 = *(const float4*)&U[(size_t)col * RANK + r];
        u[r] = t4.x; u[r + 1] = t4.y; u[r + 2] = t4.z; u[r + 3] = t4.w;
    }
    float v[64];
#pragma unroll
    for (int j = 0; j < 64; j += 4) {
        float4 t4 = *(const float4*)&V[(size_t)rr * DH + colbase + qq * 64 + j];
        v[j] = t4.x; v[j + 1] = t4.y; v[j + 2] = t4.z; v[j + 3] = t4.w;
    }

    for (int i = tid; i < CL * BGRP * RANK; i += 256)
        (&pbuf[0][0][0][0])[i] = 0.0f;

    const uint32_t mymbar = smem_u32(&mbar);
    if (tid == 0)
        asm volatile("mbarrier.init.shared.b64 [%0], %1;"
                     :: "r"(mymbar), "r"((unsigned)CL) : "memory");

    uint32_t mybuf = smem_u32(&pbuf[0][0][0][0]);
    uint32_t peerbuf[CL], peerbar[CL];
#pragma unroll
    for (int k = 0; k < CL; k++) {
        asm("mapa.shared::cluster.u32 %0, %1, %2;"
            : "=r"(peerbuf[k]) : "r"(mybuf), "r"(k));
        asm("mapa.shared::cluster.u32 %0, %1, %2;"
            : "=r"(peerbar[k]) : "r"(mymbar), "r"(k));
    }
    __syncthreads();
    asm volatile("barrier.cluster.arrive.aligned;" ::: "memory");
    asm volatile("barrier.cluster.wait.aligned;" ::: "memory");

    float c0 = hidden[(size_t)b0 * DH + col];
    float c1 = hidden[(size_t)(b0 + 1) * DH + col];

    for (int t = 1; t <= T_STEPS; ++t) {
        float* row = hidden + (size_t)(t - 1) * BATCH * DH;

        // wait for p_{t-1} partials; per-thread cluster acquire (no fence/bar)
        if (t >= 2)
            mbar_wait_acq_cluster(mymbar, (unsigned)(t & 1));

        const int par = (t - 1) & 1;
        if (tid < BGRP * RANK) {
            int b = tid >> 6, r = tid & 63;
            pcur[b][r] = pbuf[par][0][b][r] + pbuf[par][1][b][r]
                       + pbuf[par][2][b][r] + pbuf[par][3][b][r];
        }
        __syncthreads();

        float g0 = c0, g1 = c1;
        const float4* pa4 = (const float4*)pcur[0];
        const float4* pb4 = (const float4*)pcur[1];
#pragma unroll
        for (int r4 = 0; r4 < 16; ++r4) {
            float4 pa = pa4[r4];
            float4 pb = pb4[r4];
            g0 += u[4 * r4 + 0] * pa.x; g1 += u[4 * r4 + 0] * pb.x;
            g0 += u[4 * r4 + 1] * pa.y; g1 += u[4 * r4 + 1] * pb.y;
            g0 += u[4 * r4 + 2] * pa.z; g1 += u[4 * r4 + 2] * pb.z;
            g0 += u[4 * r4 + 3] * pa.w; g1 += u[4 * r4 + 3] * pb.w;
        }
        float h0 = fmaxf(g0, 0.0f);
        float h1 = fmaxf(g1, 0.0f);
        row[(size_t)b0 * DH + col] = h0;
        row[(size_t)(b0 + 1) * DH + col] = h1;
        sH[0][tid] = h0;
        sH[1][tid] = h1;

        if (t < T_STEPS) {
            const float* rowN = hidden + (size_t)t * BATCH * DH;
            c0 = rowN[(size_t)b0 * DH + col];
            c1 = rowN[(size_t)(b0 + 1) * DH + col];
        }
        __syncthreads();

        float a0 = 0.0f, a1 = 0.0f;
        const float4* h0q = (const float4*)&sH[0][qq * 64];
        const float4* h1q = (const float4*)&sH[1][qq * 64];
#pragma unroll
        for (int j4 = 0; j4 < 16; ++j4) {
            float4 ha = h0q[j4];
            float4 hb = h1q[j4];
            a0 += v[4 * j4 + 0] * ha.x; a1 += v[4 * j4 + 0] * hb.x;
            a0 += v[4 * j4 + 1] * ha.y; a1 += v[4 * j4 + 1] * hb.y;
            a0 += v[4 * j4 + 2] * ha.z; a1 += v[4 * j4 + 2] * hb.z;
            a0 += v[4 * j4 + 3] * ha.w; a1 += v[4 * j4 + 3] * hb.w;
        }
        sTmp[qq][0][rr] = a0;
        sTmp[qq][1][rr] = a1;
        __syncthreads();

        const int wpar = t & 1;
        if (tid < BGRP * RANK) {
            int b = tid >> 6, r = tid & 63;
            float s = sTmp[0][b][r] + sTmp[1][b][r]
                    + sTmp[2][b][r] + sTmp[3][b][r];
            uint32_t off =
                (uint32_t)(((wpar * CL + rank) * BGRP + b) * RANK + r) * 4u;
#pragma unroll
            for (int k = 0; k < CL; k++)
                asm volatile("st.shared::cluster.f32 [%0], %1;"
                             :: "r"(peerbuf[k] + off), "f"(s) : "memory");
        }
        __syncthreads();
        if (tid == 0) {
            asm volatile("fence.acq_rel.cluster;" ::: "memory");
#pragma unroll
            for (int k = 0; k < CL; k++)
                asm volatile("mbarrier.arrive.shared::cluster.b64 _, [%0];"
                             :: "r"(peerbar[k]) : "memory");
        }
    }

    asm volatile("barrier.cluster.arrive.aligned;" ::: "memory");
    asm volatile("barrier.cluster.wait.aligned;" ::: "memory");
}

// ---------------- launch -----------------------------------------------------
extern "C" void kernel_launch(void* const* d_in, const int* in_sizes, int n_in,
                              void* d_out, int out_size) {
    (void)in_sizes; (void)n_in; (void)out_size;
    const float* x  = (const float*)d_in[0];
    const float* Wi = (const float*)d_in[1];
    const float* U  = (const float*)d_in[2];
    const float* V  = (const float*)d_in[3];
    const float* bh = (const float*)d_in[4];
    const float* Wo = (const float*)d_in[5];
    const float* bo = (const float*)d_in[6];

    float* hidden = (float*)d_out;                                   // [T,B,DH]
    float* outp   = hidden + (size_t)T_STEPS * BATCH * DH;           // [T,B,DOUT]

    // c = x @ Wi^T + bh  (bf16x3 HMMA; written into hidden region)
    dim3 gA(T_STEPS * BATCH / 128, DH / 128);
    mma_bt<<<gA, 256>>>(x, Wi, bh, hidden, DH, DIN);

    // serial recurrence: 32 clusters x 4 CTAs, DSMEM rank exchange
    rnn_recur<<<BATCH / BGRP * CL, 256>>>(U, V, hidden);

    // output = hidden @ Wo^T + bo  (bf16x3 HMMA)
    dim3 gC(T_STEPS * BATCH / 128, DOUT / 128);
    mma_bt<<<gC, 256>>>(hidden, Wo, bo, outp, DOUT, DH);
}

// round 16
// speedup vs baseline: 1.0431x; 1.0431x over previous
#include <cuda_runtime.h>
#include <cuda_bf16.h>
#include <cstdint>

#define T_STEPS 512
#define BATCH   64
#define DIN     128
#define DH      1024
#define DOUT    256
#define RANK    64

#define CL      4            // cluster size (CTAs per batch-pair)
#define COLS    256          // DH / CL columns per CTA
#define BGRP    2            // batch elements per cluster

// ---------------- bf16x3 split-GEMM via mma.sync (HMMA) ----------------------
// C[m,n] = bias[n] + sum_k A[m,k]*B[n,k],  A:[M,K] row-major, B:[N,K] row-major.
// fp32 operands split in-kernel into bf16 hi+lo; C = Ah*Bh + Ah*Bl + Al*Bh.
// Tile 128x128, K-chunk 32, 8 warps (4m x 2n), warp = 32x64 = 2x8 m16n8k16.
// (R14 version: no register prefetch — 2 CTAs/SM hide the load latency.)
#define KT 32
#define KPAD 40              // bf16 row stride (80 B): conflict-free frag loads

__device__ __forceinline__ void store_split(__nv_bfloat16* hp,
                                            __nv_bfloat16* lp, float4 v) {
    __nv_bfloat16 h0 = __float2bfloat16(v.x);
    __nv_bfloat16 h1 = __float2bfloat16(v.y);
    __nv_bfloat16 h2 = __float2bfloat16(v.z);
    __nv_bfloat16 h3 = __float2bfloat16(v.w);
    __nv_bfloat16 l0 = __float2bfloat16(v.x - __bfloat162float(h0));
    __nv_bfloat16 l1 = __float2bfloat16(v.y - __bfloat162float(h1));
    __nv_bfloat16 l2 = __float2bfloat16(v.z - __bfloat162float(h2));
    __nv_bfloat16 l3 = __float2bfloat16(v.w - __bfloat162float(h3));
    uint2 uh, ul;
    uh.x = ((uint32_t)__bfloat16_as_ushort(h1) << 16) | __bfloat16_as_ushort(h0);
    uh.y = ((uint32_t)__bfloat16_as_ushort(h3) << 16) | __bfloat16_as_ushort(h2);
    ul.x = ((uint32_t)__bfloat16_as_ushort(l1) << 16) | __bfloat16_as_ushort(l0);
    ul.y = ((uint32_t)__bfloat16_as_ushort(l3) << 16) | __bfloat16_as_ushort(l2);
    *(uint2*)hp = uh;
    *(uint2*)lp = ul;
}

__device__ __forceinline__ void mma16816(float* c, const uint32_t* a,
                                         const uint32_t* b) {
    asm volatile(
        "mma.sync.aligned.m16n8k16.row.col.f32.bf16.bf16.f32 "
        "{%0,%1,%2,%3}, {%4,%5,%6,%7}, {%8,%9}, {%0,%1,%2,%3};"
        : "+f"(c[0]), "+f"(c[1]), "+f"(c[2]), "+f"(c[3])
        : "r"(a[0]), "r"(a[1]), "r"(a[2]), "r"(a[3]), "r"(b[0]), "r"(b[1]));
}

__global__ void __launch_bounds__(256) mma_bt(const float* __restrict__ A,
                                              const float* __restrict__ Bm,
                                              const float* __restrict__ bias,
                                              float* __restrict__ C,
                                              int N, int K) {
    __shared__ __nv_bfloat16 sAh[128][KPAD], sAl[128][KPAD];
    __shared__ __nv_bfloat16 sBh[128][KPAD], sBl[128][KPAD];

    const int tid  = threadIdx.x;
    const int lane = tid & 31;
    const int w    = tid >> 5;
    const int wm   = w & 3;            // warp m 0..3 (32 rows each)
    const int wn   = w >> 2;           // warp n 0..1 (64 cols each)
    const int m0 = blockIdx.x * 128;
    const int n0 = blockIdx.y * 128;

    const int lrow = tid >> 1;         // loader row 0..127
    const int lk   = (tid & 1) * 16;   // loader k offset

    float acc[2][8][4];
#pragma unroll
    for (int mi = 0; mi < 2; mi++)
#pragma unroll
        for (int ni = 0; ni < 8; ni++)
#pragma unroll
            for (int q = 0; q < 4; q++) acc[mi][ni][q] = 0.0f;

    const int fr = lane >> 2;          // fragment row (0..7)
    const int fc = (lane & 3) * 2;     // fragment k-col base

#pragma unroll 1
    for (int kc = 0; kc < K; kc += KT) {
        // ---- load fp32, split to bf16 hi/lo, store to SMEM ----
        const float* ap = A + (size_t)(m0 + lrow) * K + kc + lk;
        const float* bp = Bm + (size_t)(n0 + lrow) * K + kc + lk;
#pragma unroll
        for (int j = 0; j < 4; j++) {
            float4 av = *(const float4*)(ap + 4 * j);
            float4 bv = *(const float4*)(bp + 4 * j);
            store_split(&sAh[lrow][lk + 4 * j], &sAl[lrow][lk + 4 * j], av);
            store_split(&sBh[lrow][lk + 4 * j], &sBl[lrow][lk + 4 * j], bv);
        }
        __syncthreads();

        // ---- 2 k16 steps, 2x8 tiles, 3 products each ----
#pragma unroll
        for (int ks = 0; ks < 2; ks++) {
            const int c = ks * 16 + fc;
            uint32_t ah[2][4], al[2][4], bh[8][2], bl[8][2];
#pragma unroll
            for (int mi = 0; mi < 2; mi++) {
                const int r = wm * 32 + mi * 16 + fr;
                ah[mi][0] = *(const uint32_t*)&sAh[r][c];
                ah[mi][1] = *(const uint32_t*)&sAh[r + 8][c];
                ah[mi][2] = *(const uint32_t*)&sAh[r][c + 8];
                ah[mi][3] = *(const uint32_t*)&sAh[r + 8][c + 8];
                al[mi][0] = *(const uint32_t*)&sAl[r][c];
                al[mi][1] = *(const uint32_t*)&sAl[r + 8][c];
                al[mi][2] = *(const uint32_t*)&sAl[r][c + 8];
                al[mi][3] = *(const uint32_t*)&sAl[r + 8][c + 8];
            }
#pragma unroll
            for (int ni = 0; ni < 8; ni++) {
                const int nn = wn * 64 + ni * 8 + fr;
                bh[ni][0] = *(const uint32_t*)&sBh[nn][c];
                bh[ni][1] = *(const uint32_t*)&sBh[nn][c + 8];
                bl[ni][0] = *(const uint32_t*)&sBl[nn][c];
                bl[ni][1] = *(const uint32_t*)&sBl[nn][c + 8];
            }
#pragma unroll
            for (int mi = 0; mi < 2; mi++)
#pragma unroll
                for (int ni = 0; ni < 8; ni++) {
                    mma16816(acc[mi][ni], ah[mi], bh[ni]);
                    mma16816(acc[mi][ni], ah[mi], bl[ni]);
                    mma16816(acc[mi][ni], al[mi], bh[ni]);
                }
        }
        __syncthreads();
    }

    // ---- epilogue: bias + store ----
#pragma unroll
    for (int mi = 0; mi < 2; mi++) {
        const int r0 = m0 + wm * 32 + mi * 16 + fr;
#pragma unroll
        for (int ni = 0; ni < 8; ni++) {
            const int col = n0 + wn * 64 + ni * 8 + (lane & 3) * 2;
            const float b0v = bias[col];
            const float b1v = bias[col + 1];
            float2 o0 = make_float2(acc[mi][ni][0] + b0v, acc[mi][ni][1] + b1v);
            float2 o1 = make_float2(acc[mi][ni][2] + b0v, acc[mi][ni][3] + b1v);
            *(float2*)&C[(size_t)r0 * N + col] = o0;
            *(float2*)&C[(size_t)(r0 + 8) * N + col] = o1;
        }
    }
}

// ---------------- common PTX helpers ----------------------------------------
__device__ __forceinline__ uint32_t smem_u32(const void* p) {
    uint32_t a;
    asm("{ .reg .u64 t; cvta.to.shared.u64 t, %1; cvt.u32.u64 %0, t; }"
        : "=r"(a) : "l"(p));
    return a;
}

// per-thread spin with CLUSTER-scope acquire: makes peers' DSMEM stores
// (release-ordered by their fence-before-arrive) visible without a separate
// fence + __syncthreads on the consumer side.
__device__ __forceinline__ void mbar_wait_acq_cluster(uint32_t mbar,
                                                      uint32_t parity) {
    asm volatile(
        "{\n\t"
        ".reg .pred P;\n\t"
        "W%=:\n\t"
        "mbarrier.try_wait.parity.acquire.cluster.shared::cta.b64 P, [%0], %1, 0x989680;\n\t"
        "@P bra D%=;\n\t"
        "bra W%=;\n\t"
        "D%=:\n\t"
        "}"
        :: "r"(mbar), "r"(parity) : "memory");
}

// ---------------- clustered recurrence (R15 trimmed-sync version) ------------
__global__ void __launch_bounds__(256, 1) __cluster_dims__(CL, 1, 1)
rnn_recur(const float* __restrict__ U, const float* __restrict__ V,
          float* __restrict__ hidden) {
    __shared__ __align__(16) float pbuf[2][CL][BGRP][RANK];
    __shared__ __align__(16) float pcur[BGRP][RANK];
    __shared__ __align__(16) float sH[BGRP][COLS];
    __shared__ __align__(16) float sTmp[CL][BGRP][RANK];
    __shared__ __align__(8) unsigned long long mbar;

    const int tid  = threadIdx.x;
    const int rank = blockIdx.x & (CL - 1);
    const int clus = blockIdx.x >> 2;
    const int b0   = clus * BGRP;
    const int colbase = rank * COLS;
    const int col  = colbase + tid;

    const int rr = tid & 63;
    const int qq = tid >> 6;

    float u[RANK];
#pragma unroll
    for (int r = 0; r < RANK; r += 4) {
        float4 t4 = *(const float4*)&U[(size_t)col * RANK + r];
        u[r] = t4.x; u[r + 1] = t4.y; u[r + 2] = t4.z; u[r + 3] = t4.w;
    }
    float v[64];
#pragma unroll
    for (int j = 0; j < 64; j += 4) {
        float4 t4 = *(const float4*)&V[(size_t)rr * DH + colbase + qq * 64 + j];
        v[j] = t4.x; v[j + 1] = t4.y; v[j + 2] = t4.z; v[j + 3] = t4.w;
    }

    for (int i = tid; i < CL * BGRP * RANK; i += 256)
        (&pbuf[0][0][0][0])[i] = 0.0f;

    const uint32_t mymbar = smem_u32(&mbar);
    if (tid == 0)
        asm volatile("mbarrier.init.shared.b64 [%0], %1;"
                     :: "r"(mymbar), "r"((unsigned)CL) : "memory");

    uint32_t mybuf = smem_u32(&pbuf[0][0][0][0]);
    uint32_t peerbuf[CL], peerbar[CL];
#pragma unroll
    for (int k = 0; k < CL; k++) {
        asm("mapa.shared::cluster.u32 %0, %1, %2;"
            : "=r"(peerbuf[k]) : "r"(mybuf), "r"(k));
        asm("mapa.shared::cluster.u32 %0, %1, %2;"
            : "=r"(peerbar[k]) : "r"(mymbar), "r"(k));
    }
    __syncthreads();
    asm volatile("barrier.cluster.arrive.aligned;" ::: "memory");
    asm volatile("barrier.cluster.wait.aligned;" ::: "memory");

    float c0 = hidden[(size_t)b0 * DH + col];
    float c1 = hidden[(size_t)(b0 + 1) * DH + col];

    for (int t = 1; t <= T_STEPS; ++t) {
        float* row = hidden + (size_t)(t - 1) * BATCH * DH;

        // wait for p_{t-1} partials; per-thread cluster acquire (no fence/bar)
        if (t >= 2)
            mbar_wait_acq_cluster(mymbar, (unsigned)(t & 1));

        const int par = (t - 1) & 1;
        if (tid < BGRP * RANK) {
            int b = tid >> 6, r = tid & 63;
            pcur[b][r] = pbuf[par][0][b][r] + pbuf[par][1][b][r]
                       + pbuf[par][2][b][r] + pbuf[par][3][b][r];
        }
        __syncthreads();

        float g0 = c0, g1 = c1;
        const float4* pa4 = (const float4*)pcur[0];
        const float4* pb4 = (const float4*)pcur[1];
#pragma unroll
        for (int r4 = 0; r4 < 16; ++r4) {
            float4 pa = pa4[r4];
            float4 pb = pb4[r4];
            g0 += u[4 * r4 + 0] * pa.x; g1 += u[4 * r4 + 0] * pb.x;
            g0 += u[4 * r4 + 1] * pa.y; g1 += u[4 * r4 + 1] * pb.y;
            g0 += u[4 * r4 + 2] * pa.z; g1 += u[4 * r4 + 2] * pb.z;
            g0 += u[4 * r4 + 3] * pa.w; g1 += u[4 * r4 + 3] * pb.w;
        }
        float h0 = fmaxf(g0, 0.0f);
        float h1 = fmaxf(g1, 0.0f);
        row[(size_t)b0 * DH + col] = h0;
        row[(size_t)(b0 + 1) * DH + col] = h1;
        sH[0][tid] = h0;
        sH[1][tid] = h1;

        if (t < T_STEPS) {
            const float* rowN = hidden + (size_t)t * BATCH * DH;
            c0 = rowN[(size_t)b0 * DH + col];
            c1 = rowN[(size_t)(b0 + 1) * DH + col];
        }
        __syncthreads();

        float a0 = 0.0f, a1 = 0.0f;
        const float4* h0q = (const float4*)&sH[0][qq * 64];
        const float4* h1q = (const float4*)&sH[1][qq * 64];
#pragma unroll
        for (int j4 = 0; j4 < 16; ++j4) {
            float4 ha = h0q[j4];
            float4 hb = h1q[j4];
            a0 += v[4 * j4 + 0] * ha.x; a1 += v[4 * j4 + 0] * hb.x;
            a0 += v[4 * j4 + 1] * ha.y; a1 += v[4 * j4 + 1] * hb.y;
            a0 += v[4 * j4 + 2] * ha.z; a1 += v[4 * j4 + 2] * hb.z;
            a0 += v[4 * j4 + 3] * ha.w; a1 += v[4 * j4 + 3] * hb.w;
        }
        sTmp[qq][0][rr] = a0;
        sTmp[qq][1][rr] = a1;
        __syncthreads();

        const int wpar = t & 1;
        if (tid < BGRP * RANK) {
            int b = tid >> 6, r = tid & 63;
            float s = sTmp[0][b][r] + sTmp[1][b][r]
                    + sTmp[2][b][r] + sTmp[3][b][r];
            uint32_t off =
                (uint32_t)(((wpar * CL + rank) * BGRP + b) * RANK + r) * 4u;
#pragma unroll
            for (int k = 0; k < CL; k++)
                asm volatile("st.shared::cluster.f32 [%0], %1;"
                             :: "r"(peerbuf[k] + off), "f"(s) : "memory");
        }
        __syncthreads();
        if (tid == 0) {
            asm volatile("fence.acq_rel.cluster;" ::: "memory");
#pragma unroll
            for (int k = 0; k < CL; k++)
                asm volatile("mbarrier.arrive.shared::cluster.b64 _, [%0];"
                             :: "r"(peerbar[k]) : "memory");
        }
    }

    asm volatile("barrier.cluster.arrive.aligned;" ::: "memory");
    asm volatile("barrier.cluster.wait.aligned;" ::: "memory");
}

// ---------------- launch -----------------------------------------------------
extern "C" void kernel_launch(void* const* d_in, const int* in_sizes, int n_in,
                              void* d_out, int out_size) {
    (void)in_sizes; (void)n_in; (void)out_size;
    const float* x  = (const float*)d_in[0];
    const float* Wi = (const float*)d_in[1];
    const float* U  = (const float*)d_in[2];
    const float* V  = (const float*)d_in[3];
    const float* bh = (const float*)d_in[4];
    const float* Wo = (const float*)d_in[5];
    const float* bo = (const float*)d_in[6];

    float* hidden = (float*)d_out;                                   // [T,B,DH]
    float* outp   = hidden + (size_t)T_STEPS * BATCH * DH;           // [T,B,DOUT]

    // c = x @ Wi^T + bh  (bf16x3 HMMA; written into hidden region)
    dim3 gA(T_STEPS * BATCH / 128, DH / 128);
    mma_bt<<<gA, 256>>>(x, Wi, bh, hidden, DH, DIN);

    // serial recurrence: 32 clusters x 4 CTAs, DSMEM rank exchange
    rnn_recur<<<BATCH / BGRP * CL, 256>>>(U, V, hidden);

    // output = hidden @ Wo^T + bo  (bf16x3 HMMA)
    dim3 gC(T_STEPS * BATCH / 128, DOUT / 128);
    mma_bt<<<gC, 256>>>(hidden, Wo, bo, outp, DOUT, DH);
}